// round 1
// baseline (speedup 1.0000x reference)
#include <cuda_runtime.h>
#include <cuda_bf16.h>
#include <math.h>

// Problem constants
#define Bq 8
#define Sq 1024
#define Eq 768
#define Hq 12
#define Dq 64
#define Mq 3072
#define NTOK (Bq*Sq)          // 8192
#define QKVC (3*Eq)           // 2304

// ---------------- scratch (device globals; no allocs allowed) ----------------
__device__ float g_qkv[NTOK*QKVC];   // [token, 3E] packed q|k|v per head
__device__ float g_ctx[NTOK*Eq];     // attention output [token, H*D]
__device__ float g_y1 [NTOK*Eq];     // x + proj(ctx)
__device__ float g_x1 [NTOK*Eq];     // LN1(y1)
__device__ float g_h  [NTOK*Mq];     // gelu(fc1)

// ---------------- generic SIMT GEMM:  C[N,Mo] = A[N,K] @ W[Mo,K]^T + epi -----
// EPI: 0 = +bias ; 1 = +bias, gelu ; 2 = +bias, +res
template<int EPI>
__global__ void gemm_kernel(const float* __restrict__ A,
                            const float* __restrict__ W,
                            const float* __restrict__ bias,
                            const float* __restrict__ res,
                            float* __restrict__ C,
                            int N, int K, int Mo)
{
    constexpr int BM = 64, BN = 64, BK = 16;
    __shared__ float As[BK][BM + 1];
    __shared__ float Bs[BK][BN + 1];

    const int tid = threadIdx.x;            // 256 threads
    const int m0 = blockIdx.y * BM;
    const int n0 = blockIdx.x * BN;
    const int ty = tid >> 4;                 // 0..15
    const int tx = tid & 15;                 // 0..15
    const int lrow = tid >> 2;               // 0..63   (tile row to load)
    const int lk   = (tid & 3) * 4;          // 0,4,8,12

    float acc[4][4];
    #pragma unroll
    for (int i = 0; i < 4; i++)
        #pragma unroll
        for (int j = 0; j < 4; j++) acc[i][j] = 0.f;

    for (int k0 = 0; k0 < K; k0 += BK) {
        float4 av = *(const float4*)(A + (m0 + lrow) * K + k0 + lk);
        float4 wv = *(const float4*)(W + (n0 + lrow) * K + k0 + lk);
        As[lk+0][lrow] = av.x; As[lk+1][lrow] = av.y;
        As[lk+2][lrow] = av.z; As[lk+3][lrow] = av.w;
        Bs[lk+0][lrow] = wv.x; Bs[lk+1][lrow] = wv.y;
        Bs[lk+2][lrow] = wv.z; Bs[lk+3][lrow] = wv.w;
        __syncthreads();

        #pragma unroll
        for (int k = 0; k < BK; k++) {
            float a[4], b[4];
            #pragma unroll
            for (int i = 0; i < 4; i++) a[i] = As[k][ty + 16*i];
            #pragma unroll
            for (int j = 0; j < 4; j++) b[j] = Bs[k][tx + 16*j];
            #pragma unroll
            for (int i = 0; i < 4; i++)
                #pragma unroll
                for (int j = 0; j < 4; j++) acc[i][j] += a[i] * b[j];
        }
        __syncthreads();
    }

    #pragma unroll
    for (int i = 0; i < 4; i++) {
        const int m = m0 + ty + 16*i;
        #pragma unroll
        for (int j = 0; j < 4; j++) {
            const int n = n0 + tx + 16*j;
            float v = acc[i][j] + bias[n];
            if (EPI == 1) {
                // exact gelu: 0.5*v*(1+erf(v/sqrt(2)))
                v = 0.5f * v * (1.0f + erff(v * 0.70710678118654752f));
            }
            if (EPI == 2) {
                v += res[(size_t)m * Mo + n];
            }
            C[(size_t)m * Mo + n] = v;
        }
    }
}

// ---------------- 2D RoPE applied in-place to q and k in g_qkv ----------------
__global__ void rope_kernel(float* __restrict__ qkv,
                            const float* __restrict__ cosT,
                            const float* __restrict__ sinT)
{
    int idx = blockIdx.x * blockDim.x + threadIdx.x;      // NTOK*H*32
    if (idx >= NTOK * Hq * (Dq/2)) return;
    const int pair  = idx & 31;
    int rest        = idx >> 5;
    const int h     = rest % Hq;
    const int tok   = rest / Hq;
    const int s     = tok & (Sq - 1);

    const int base = tok * QKVC + h * Dq + pair * 2;
    const int tb   = s * Dq + pair * 2;
    const float c0 = cosT[tb],     c1 = cosT[tb + 1];
    const float s0 = sinT[tb],     s1 = sinT[tb + 1];

    // q
    float t0 = qkv[base], t1 = qkv[base + 1];
    qkv[base]     = t0 * c0 - t1 * s0;
    qkv[base + 1] = t1 * c1 + t0 * s1;
    // k (offset +E within the packed row)
    t0 = qkv[base + Eq]; t1 = qkv[base + Eq + 1];
    qkv[base + Eq]     = t0 * c0 - t1 * s0;
    qkv[base + Eq + 1] = t1 * c1 + t0 * s1;
}

// ---------------- flash attention (online softmax), fp32 ----------------------
// block = (q-tile of 32 rows, head h, batch b); 256 threads
// thread: row = tid>>3 (0..31), cg = tid&7 -> owns 4 score cols, 8 out dims
__global__ void attn_kernel(const float* __restrict__ qkv,
                            const unsigned char* __restrict__ mask,
                            float* __restrict__ ctx)
{
    __shared__ float Qs[32][65];
    __shared__ float Ks[32][65];
    __shared__ float Vs[32][65];
    __shared__ float Ps[32][33];

    const int qt = blockIdx.x;      // 0..31
    const int h  = blockIdx.y;      // 0..11
    const int b  = blockIdx.z;      // 0..7
    const int tid = threadIdx.x;
    const int row = tid >> 3;
    const int cg  = tid & 7;
    const int q0  = qt * 32;

    // load Q tile (rotated q) : 32x64, vectorized
    {
        const int e0 = tid * 2;   // two float4 per thread: 512 float4 total
        #pragma unroll
        for (int u = 0; u < 2; u++) {
            int e = e0 + u;
            int r = e >> 4;
            int c = (e & 15) * 4;
            float4 v = *(const float4*)(qkv + (b*Sq + q0 + r) * QKVC + h * Dq + c);
            Qs[r][c]   = v.x; Qs[r][c+1] = v.y;
            Qs[r][c+2] = v.z; Qs[r][c+3] = v.w;
        }
    }

    float m = -1e30f, l = 0.f;
    float O[8];
    #pragma unroll
    for (int j = 0; j < 8; j++) O[j] = 0.f;

    const float scale = 0.125f;   // D^-0.5

    for (int k0 = 0; k0 < Sq; k0 += 32) {
        __syncthreads();   // previous iteration's Ks/Vs/Ps consumption done
        // load K,V tiles 32x64 each
        {
            const int e0 = tid * 2;
            #pragma unroll
            for (int u = 0; u < 2; u++) {
                int e = e0 + u;
                int r = e >> 4;
                int c = (e & 15) * 4;
                const float* kp = qkv + (b*Sq + k0 + r) * QKVC + Eq + h * Dq + c;
                float4 kv = *(const float4*)kp;
                float4 vv = *(const float4*)(kp + Eq);
                Ks[r][c]   = kv.x; Ks[r][c+1] = kv.y;
                Ks[r][c+2] = kv.z; Ks[r][c+3] = kv.w;
                Vs[r][c]   = vv.x; Vs[r][c+1] = vv.y;
                Vs[r][c+2] = vv.z; Vs[r][c+3] = vv.w;
            }
        }
        __syncthreads();

        // scores for 4 cols
        float sc[4] = {0.f, 0.f, 0.f, 0.f};
        #pragma unroll 4
        for (int d = 0; d < 64; d++) {
            float qv = Qs[row][d];
            #pragma unroll
            for (int c = 0; c < 4; c++)
                sc[c] += qv * Ks[cg*4 + c][d];
        }
        #pragma unroll
        for (int c = 0; c < 4; c++) {
            sc[c] *= scale;
            if (mask[b*Sq + k0 + cg*4 + c]) sc[c] = -1e30f;
        }

        // row max across 8 threads (width 8 segments are warp-aligned)
        float tmax = fmaxf(fmaxf(sc[0], sc[1]), fmaxf(sc[2], sc[3]));
        #pragma unroll
        for (int o = 4; o; o >>= 1)
            tmax = fmaxf(tmax, __shfl_xor_sync(0xffffffffu, tmax, o, 8));

        float mn = fmaxf(m, tmax);
        float p[4], psum = 0.f;
        #pragma unroll
        for (int c = 0; c < 4; c++) { p[c] = __expf(sc[c] - mn); psum += p[c]; }
        #pragma unroll
        for (int o = 4; o; o >>= 1)
            psum += __shfl_xor_sync(0xffffffffu, psum, o, 8);

        float corr = __expf(m - mn);
        l = l * corr + psum;
        m = mn;
        #pragma unroll
        for (int j = 0; j < 8; j++) O[j] *= corr;

        #pragma unroll
        for (int c = 0; c < 4; c++) Ps[row][cg*4 + c] = p[c];
        __syncthreads();

        // O += P @ V
        #pragma unroll 4
        for (int k = 0; k < 32; k++) {
            float pv = Ps[row][k];
            #pragma unroll
            for (int j = 0; j < 8; j++)
                O[j] += pv * Vs[k][cg*8 + j];
        }
    }

    const float inv = 1.f / l;
    #pragma unroll
    for (int j = 0; j < 8; j++)
        ctx[((b*Sq + q0 + row) * Hq + h) * Dq + cg*8 + j] = O[j] * inv;
}

// ---------------- LayerNorm over last dim 768, one block per row --------------
__global__ void ln_kernel(const float* __restrict__ in,
                          const float* __restrict__ g,
                          const float* __restrict__ b,
                          float* __restrict__ out)
{
    const int row = blockIdx.x;
    const int t   = threadIdx.x;            // 256
    const float* p = in + (size_t)row * Eq;

    float v0 = p[t], v1 = p[t + 256], v2 = p[t + 512];
    float s  = v0 + v1 + v2;
    float s2 = v0*v0 + v1*v1 + v2*v2;
    #pragma unroll
    for (int o = 16; o; o >>= 1) {
        s  += __shfl_xor_sync(0xffffffffu, s,  o);
        s2 += __shfl_xor_sync(0xffffffffu, s2, o);
    }
    __shared__ float sh[2][8];
    if ((t & 31) == 0) { sh[0][t >> 5] = s; sh[1][t >> 5] = s2; }
    __syncthreads();
    float ts = 0.f, ts2 = 0.f;
    #pragma unroll
    for (int i = 0; i < 8; i++) { ts += sh[0][i]; ts2 += sh[1][i]; }

    const float mean = ts * (1.f / Eq);
    const float var  = ts2 * (1.f / Eq) - mean * mean;
    const float r    = rsqrtf(var + 1e-5f);

    float* o = out + (size_t)row * Eq;
    o[t]       = (v0 - mean) * r * g[t]       + b[t];
    o[t + 256] = (v1 - mean) * r * g[t + 256] + b[t + 256];
    o[t + 512] = (v2 - mean) * r * g[t + 512] + b[t + 512];
}

// ------------------------------- launch ---------------------------------------
extern "C" void kernel_launch(void* const* d_in, const int* in_sizes, int n_in,
                              void* d_out, int out_size)
{
    const float* x       = (const float*)d_in[0];
    const unsigned char* mask = (const unsigned char*)d_in[1];
    const float* qkv_w   = (const float*)d_in[2];
    const float* qkv_b   = (const float*)d_in[3];
    const float* proj_w  = (const float*)d_in[4];
    const float* proj_b  = (const float*)d_in[5];
    const float* ln1_g   = (const float*)d_in[6];
    const float* ln1_b   = (const float*)d_in[7];
    const float* w1      = (const float*)d_in[8];
    const float* b1      = (const float*)d_in[9];
    const float* w2      = (const float*)d_in[10];
    const float* b2      = (const float*)d_in[11];
    const float* ln2_g   = (const float*)d_in[12];
    const float* ln2_b   = (const float*)d_in[13];
    const float* rope_c  = (const float*)d_in[14];
    const float* rope_s  = (const float*)d_in[15];
    float* out = (float*)d_out;

    float *qkv, *ctx, *y1, *x1, *hb;
    cudaGetSymbolAddress((void**)&qkv, g_qkv);
    cudaGetSymbolAddress((void**)&ctx, g_ctx);
    cudaGetSymbolAddress((void**)&y1,  g_y1);
    cudaGetSymbolAddress((void**)&x1,  g_x1);
    cudaGetSymbolAddress((void**)&hb,  g_h);

    // 1. QKV projection + bias
    gemm_kernel<0><<<dim3(QKVC/64, NTOK/64), 256>>>(x, qkv_w, qkv_b, nullptr,
                                                    qkv, NTOK, Eq, QKVC);
    // 2. RoPE on q,k
    {
        int n = NTOK * Hq * (Dq/2);
        rope_kernel<<<(n + 255)/256, 256>>>(qkv, rope_c, rope_s);
    }
    // 3. attention
    attn_kernel<<<dim3(Sq/32, Hq, Bq), 256>>>(qkv, mask, ctx);
    // 4. out-proj + bias + residual(x)  -> y1
    gemm_kernel<2><<<dim3(Eq/64, NTOK/64), 256>>>(ctx, proj_w, proj_b, x,
                                                  y1, NTOK, Eq, Eq);
    // 5. LN1 -> x1
    ln_kernel<<<NTOK, 256>>>(y1, ln1_g, ln1_b, x1);
    // 6. FC1 + bias + gelu -> h
    gemm_kernel<1><<<dim3(Mq/64, NTOK/64), 256>>>(x1, w1, b1, nullptr,
                                                  hb, NTOK, Eq, Mq);
    // 7. FC2 + bias + residual(x1) -> out (pre-LN2)
    gemm_kernel<2><<<dim3(Eq/64, NTOK/64), 256>>>(hb, w2, b2, x1,
                                                  out, NTOK, Mq, Eq);
    // 8. LN2 in-place on out
    ln_kernel<<<NTOK, 256>>>(out, ln2_g, ln2_b, out);
}

// round 3
// speedup vs baseline: 2.8899x; 2.8899x over previous
#include <cuda_runtime.h>
#include <cuda_bf16.h>
#include <cstdint>
#include <math.h>

#define Bq 8
#define Sq 1024
#define Eq 768
#define Hq 12
#define Dq 64
#define Mq 3072
#define NTOK (Bq*Sq)          // 8192
#define QKVC (3*Eq)           // 2304

// ---------------- scratch ----------------
__device__ float g_qkv[NTOK*QKVC];
__device__ float g_ctx[NTOK*Eq];
__device__ float g_y1 [NTOK*Eq];
__device__ float g_x1 [NTOK*Eq];
__device__ float g_h  [NTOK*Mq];

// ---------------- tf32 helpers ----------------
__device__ __forceinline__ unsigned f2tf32(float x) {
    unsigned u;
    asm("cvt.rna.tf32.f32 %0, %1;" : "=r"(u) : "f"(x));
    return u;
}

__device__ __forceinline__ void mma_tf32(float* d, const unsigned* a, const unsigned* b) {
    asm volatile(
        "mma.sync.aligned.m16n8k8.row.col.f32.tf32.tf32.f32 "
        "{%0,%1,%2,%3}, {%4,%5,%6,%7}, {%8,%9}, {%0,%1,%2,%3};"
        : "+f"(d[0]), "+f"(d[1]), "+f"(d[2]), "+f"(d[3])
        : "r"(a[0]), "r"(a[1]), "r"(a[2]), "r"(a[3]),
          "r"(b[0]), "r"(b[1]));
}

// ---------------- tf32 tensor-core GEMM: C[N,Mo] = A[N,K] @ W[Mo,K]^T -------
// Block 128x128, BK=32, 256 threads (8 warps, 4x2 of 32x64 warp tiles).
// EPI: 0=+bias ; 1=+bias,gelu ; 2=+bias,+res
template<int EPI>
__global__ __launch_bounds__(256, 1)
void gemm_tf32(const float* __restrict__ A,
               const float* __restrict__ W,
               const float* __restrict__ bias,
               const float* __restrict__ res,
               float* __restrict__ C,
               int N, int K, int Mo)
{
    constexpr int KS = 36;                   // smem k-stride (bank-safe)
    __shared__ float As[128 * KS];           // As[m][k]
    __shared__ float Bs[128 * KS];           // Bs[n][k]

    const int tid  = threadIdx.x;
    const int warp = tid >> 5, lane = tid & 31;
    const int g    = lane >> 2, t4 = lane & 3;
    const int wm   = warp >> 1, wn = warp & 1;
    const int m0w  = wm * 32,  n0w = wn * 64;
    const int bm0  = blockIdx.y * 128;
    const int bn0  = blockIdx.x * 128;

    const int arow = tid >> 1;               // 0..127
    const int acol = (tid & 1) * 16;         // 0 or 16

    const float* Ap = A + (size_t)(bm0 + arow) * K + acol;
    const float* Wp = W + (size_t)(bn0 + arow) * K + acol;

    float acc[2][8][4];
    #pragma unroll
    for (int mi = 0; mi < 2; mi++)
        #pragma unroll
        for (int ni = 0; ni < 8; ni++)
            #pragma unroll
            for (int r = 0; r < 4; r++) acc[mi][ni][r] = 0.f;

    float4 pa[4], pb[4];
    #pragma unroll
    for (int u = 0; u < 4; u++) {
        pa[u] = *(const float4*)(Ap + u * 4);
        pb[u] = *(const float4*)(Wp + u * 4);
    }

    const int T = K / 32;
    for (int t = 0; t < T; t++) {
        // stage (convert to tf32 at store time)
        #pragma unroll
        for (int u = 0; u < 4; u++) {
            float4 ca, cb;
            ca.x = __uint_as_float(f2tf32(pa[u].x));
            ca.y = __uint_as_float(f2tf32(pa[u].y));
            ca.z = __uint_as_float(f2tf32(pa[u].z));
            ca.w = __uint_as_float(f2tf32(pa[u].w));
            cb.x = __uint_as_float(f2tf32(pb[u].x));
            cb.y = __uint_as_float(f2tf32(pb[u].y));
            cb.z = __uint_as_float(f2tf32(pb[u].z));
            cb.w = __uint_as_float(f2tf32(pb[u].w));
            *(float4*)&As[arow * KS + acol + u * 4] = ca;
            *(float4*)&Bs[arow * KS + acol + u * 4] = cb;
        }
        __syncthreads();

        if (t + 1 < T) {
            const float* Ap2 = Ap + (t + 1) * 32;
            const float* Wp2 = Wp + (t + 1) * 32;
            #pragma unroll
            for (int u = 0; u < 4; u++) {
                pa[u] = *(const float4*)(Ap2 + u * 4);
                pb[u] = *(const float4*)(Wp2 + u * 4);
            }
        }

        #pragma unroll
        for (int kk = 0; kk < 32; kk += 8) {
            unsigned af[2][4], bf[8][2];
            #pragma unroll
            for (int mi = 0; mi < 2; mi++) {
                const int mr = m0w + mi * 16;
                af[mi][0] = __float_as_uint(As[(mr + g)     * KS + kk + t4]);
                af[mi][1] = __float_as_uint(As[(mr + g + 8) * KS + kk + t4]);
                af[mi][2] = __float_as_uint(As[(mr + g)     * KS + kk + t4 + 4]);
                af[mi][3] = __float_as_uint(As[(mr + g + 8) * KS + kk + t4 + 4]);
            }
            #pragma unroll
            for (int ni = 0; ni < 8; ni++) {
                const int nr = n0w + ni * 8 + g;
                bf[ni][0] = __float_as_uint(Bs[nr * KS + kk + t4]);
                bf[ni][1] = __float_as_uint(Bs[nr * KS + kk + t4 + 4]);
            }
            #pragma unroll
            for (int mi = 0; mi < 2; mi++)
                #pragma unroll
                for (int ni = 0; ni < 8; ni++)
                    mma_tf32(acc[mi][ni], af[mi], bf[ni]);
        }
        __syncthreads();
    }

    // epilogue
    #pragma unroll
    for (int mi = 0; mi < 2; mi++) {
        #pragma unroll
        for (int half = 0; half < 2; half++) {
            const int m = bm0 + m0w + mi * 16 + g + half * 8;
            #pragma unroll
            for (int ni = 0; ni < 8; ni++) {
                const int n = bn0 + n0w + ni * 8 + 2 * t4;
                float v0 = acc[mi][ni][half * 2 + 0] + bias[n];
                float v1 = acc[mi][ni][half * 2 + 1] + bias[n + 1];
                if (EPI == 1) {
                    v0 = 0.5f * v0 * (1.0f + erff(v0 * 0.70710678118654752f));
                    v1 = 0.5f * v1 * (1.0f + erff(v1 * 0.70710678118654752f));
                }
                if (EPI == 2) {
                    float2 rv = *(const float2*)(res + (size_t)m * Mo + n);
                    v0 += rv.x; v1 += rv.y;
                }
                float2 ov; ov.x = v0; ov.y = v1;
                *(float2*)(C + (size_t)m * Mo + n) = ov;
            }
        }
    }
}

// ---------------- 2D RoPE ----------------
__global__ void rope_kernel(float* __restrict__ qkv,
                            const float* __restrict__ cosT,
                            const float* __restrict__ sinT)
{
    int idx = blockIdx.x * blockDim.x + threadIdx.x;
    if (idx >= NTOK * Hq * (Dq/2)) return;
    const int pair  = idx & 31;
    int rest        = idx >> 5;
    const int h     = rest % Hq;
    const int tok   = rest / Hq;
    const int s     = tok & (Sq - 1);

    const int base = tok * QKVC + h * Dq + pair * 2;
    const int tb   = s * Dq + pair * 2;
    const float c0 = cosT[tb],     c1 = cosT[tb + 1];
    const float s0 = sinT[tb],     s1 = sinT[tb + 1];

    float t0 = qkv[base], t1 = qkv[base + 1];
    qkv[base]     = t0 * c0 - t1 * s0;
    qkv[base + 1] = t1 * c1 + t0 * s1;
    t0 = qkv[base + Eq]; t1 = qkv[base + Eq + 1];
    qkv[base + Eq]     = t0 * c0 - t1 * s0;
    qkv[base + Eq + 1] = t1 * c1 + t0 * s1;
}

// ---------------- flash attention, 64x64 tiles, 4x4 register blocking --------
#define ATT_STRIDE 68
#define ATT_SMEM   (4 * 64 * ATT_STRIDE * 4)

__global__ __launch_bounds__(256, 2)
void attn_kernel(const float* __restrict__ qkv,
                 const unsigned char* __restrict__ mask,
                 float* __restrict__ ctx)
{
    extern __shared__ float sm[];
    float* Qt = sm;
    float* Kt = sm + 64 * ATT_STRIDE;
    float* Vs = sm + 2 * 64 * ATT_STRIDE;
    float* Pt = sm + 3 * 64 * ATT_STRIDE;

    const int tid = threadIdx.x;
    const int ty = tid >> 4, tx = tid & 15;
    const int b = blockIdx.z, h = blockIdx.y;
    const int q0 = blockIdx.x * 64;

    const float* qbase = qkv + (size_t)(b * Sq) * QKVC + h * Dq;

    const int lr = tid >> 2;            // 0..63
    const int lc = (tid & 3) * 4;       // 0,4,8,12

    // load Q transposed: Qt[d][r]
    #pragma unroll
    for (int u = 0; u < 4; u++) {
        const int d = lc + u * 16;
        float4 v = *(const float4*)(qbase + (size_t)(q0 + lr) * QKVC + d);
        Qt[(d + 0) * ATT_STRIDE + lr] = v.x;
        Qt[(d + 1) * ATT_STRIDE + lr] = v.y;
        Qt[(d + 2) * ATT_STRIDE + lr] = v.z;
        Qt[(d + 3) * ATT_STRIDE + lr] = v.w;
    }

    float m_[4], l_[4], O[4][4];
    #pragma unroll
    for (int i = 0; i < 4; i++) {
        m_[i] = -1e30f; l_[i] = 0.f;
        #pragma unroll
        for (int j = 0; j < 4; j++) O[i][j] = 0.f;
    }

    const float scale = 0.125f;

    for (int k0 = 0; k0 < Sq; k0 += 64) {
        __syncthreads();
        {
            const float* kb = qbase + Eq + (size_t)(k0 + lr) * QKVC;
            #pragma unroll
            for (int u = 0; u < 4; u++) {
                const int d = lc + u * 16;
                float4 kv = *(const float4*)(kb + d);
                Kt[(d + 0) * ATT_STRIDE + lr] = kv.x;
                Kt[(d + 1) * ATT_STRIDE + lr] = kv.y;
                Kt[(d + 2) * ATT_STRIDE + lr] = kv.z;
                Kt[(d + 3) * ATT_STRIDE + lr] = kv.w;
                float4 vv = *(const float4*)(kb + Eq + d);
                *(float4*)&Vs[lr * ATT_STRIDE + d] = vv;
            }
        }
        __syncthreads();

        float sc[4][4];
        #pragma unroll
        for (int i = 0; i < 4; i++)
            #pragma unroll
            for (int j = 0; j < 4; j++) sc[i][j] = 0.f;

        #pragma unroll 4
        for (int d = 0; d < 64; d++) {
            float4 qv = *(const float4*)&Qt[d * ATT_STRIDE + ty * 4];
            float4 kv = *(const float4*)&Kt[d * ATT_STRIDE + tx * 4];
            const float qa[4] = {qv.x, qv.y, qv.z, qv.w};
            const float ka[4] = {kv.x, kv.y, kv.z, kv.w};
            #pragma unroll
            for (int i = 0; i < 4; i++)
                #pragma unroll
                for (int j = 0; j < 4; j++) sc[i][j] += qa[i] * ka[j];
        }

        const unsigned char* mrow = mask + b * Sq + k0 + tx * 4;
        #pragma unroll
        for (int j = 0; j < 4; j++) {
            const bool mk = mrow[j];
            #pragma unroll
            for (int i = 0; i < 4; i++) {
                sc[i][j] *= scale;
                if (mk) sc[i][j] = -1e30f;
            }
        }

        #pragma unroll
        for (int i = 0; i < 4; i++) {
            float tm = fmaxf(fmaxf(sc[i][0], sc[i][1]), fmaxf(sc[i][2], sc[i][3]));
            #pragma unroll
            for (int o = 8; o; o >>= 1)
                tm = fmaxf(tm, __shfl_xor_sync(0xffffffffu, tm, o, 16));
            const float mn = fmaxf(m_[i], tm);
            float ps = 0.f;
            #pragma unroll
            for (int j = 0; j < 4; j++) {
                sc[i][j] = __expf(sc[i][j] - mn);
                ps += sc[i][j];
            }
            #pragma unroll
            for (int o = 8; o; o >>= 1)
                ps += __shfl_xor_sync(0xffffffffu, ps, o, 16);
            const float corr = __expf(m_[i] - mn);
            l_[i] = l_[i] * corr + ps;
            m_[i] = mn;
            #pragma unroll
            for (int j = 0; j < 4; j++) O[i][j] *= corr;
        }

        #pragma unroll
        for (int j = 0; j < 4; j++) {
            float4 pv;
            pv.x = sc[0][j]; pv.y = sc[1][j]; pv.z = sc[2][j]; pv.w = sc[3][j];
            *(float4*)&Pt[(tx * 4 + j) * ATT_STRIDE + ty * 4] = pv;
        }
        __syncthreads();

        #pragma unroll 4
        for (int k = 0; k < 64; k++) {
            float4 pv = *(const float4*)&Pt[k * ATT_STRIDE + ty * 4];
            float4 vv = *(const float4*)&Vs[k * ATT_STRIDE + tx * 4];
            const float pa[4] = {pv.x, pv.y, pv.z, pv.w};
            const float va[4] = {vv.x, vv.y, vv.z, vv.w};
            #pragma unroll
            for (int i = 0; i < 4; i++)
                #pragma unroll
                for (int j = 0; j < 4; j++) O[i][j] += pa[i] * va[j];
        }
    }

    #pragma unroll
    for (int i = 0; i < 4; i++) {
        const float inv = 1.f / l_[i];
        float4 ov;
        ov.x = O[i][0] * inv; ov.y = O[i][1] * inv;
        ov.z = O[i][2] * inv; ov.w = O[i][3] * inv;
        *(float4*)(ctx + ((size_t)(b * Sq + q0 + ty * 4 + i) * Hq + h) * Dq + tx * 4) = ov;
    }
}

// ---------------- LayerNorm (768) ----------------
__global__ void ln_kernel(const float* __restrict__ in,
                          const float* __restrict__ g,
                          const float* __restrict__ b,
                          float* __restrict__ out)
{
    const int row = blockIdx.x;
    const int t   = threadIdx.x;
    const float* p = in + (size_t)row * Eq;

    float v0 = p[t], v1 = p[t + 256], v2 = p[t + 512];
    float s  = v0 + v1 + v2;
    float s2 = v0*v0 + v1*v1 + v2*v2;
    #pragma unroll
    for (int o = 16; o; o >>= 1) {
        s  += __shfl_xor_sync(0xffffffffu, s,  o);
        s2 += __shfl_xor_sync(0xffffffffu, s2, o);
    }
    __shared__ float sh[2][8];
    if ((t & 31) == 0) { sh[0][t >> 5] = s; sh[1][t >> 5] = s2; }
    __syncthreads();
    float ts = 0.f, ts2 = 0.f;
    #pragma unroll
    for (int i = 0; i < 8; i++) { ts += sh[0][i]; ts2 += sh[1][i]; }

    const float mean = ts * (1.f / Eq);
    const float var  = ts2 * (1.f / Eq) - mean * mean;
    const float r    = rsqrtf(var + 1e-5f);

    float* o = out + (size_t)row * Eq;
    o[t]       = (v0 - mean) * r * g[t]       + b[t];
    o[t + 256] = (v1 - mean) * r * g[t + 256] + b[t + 256];
    o[t + 512] = (v2 - mean) * r * g[t + 512] + b[t + 512];
}

// ------------------------------- launch ---------------------------------------
extern "C" void kernel_launch(void* const* d_in, const int* in_sizes, int n_in,
                              void* d_out, int out_size)
{
    const float* x       = (const float*)d_in[0];
    const unsigned char* mask = (const unsigned char*)d_in[1];
    const float* qkv_w   = (const float*)d_in[2];
    const float* qkv_b   = (const float*)d_in[3];
    const float* proj_w  = (const float*)d_in[4];
    const float* proj_b  = (const float*)d_in[5];
    const float* ln1_g   = (const float*)d_in[6];
    const float* ln1_b   = (const float*)d_in[7];
    const float* w1      = (const float*)d_in[8];
    const float* b1      = (const float*)d_in[9];
    const float* w2      = (const float*)d_in[10];
    const float* b2      = (const float*)d_in[11];
    const float* ln2_g   = (const float*)d_in[12];
    const float* ln2_b   = (const float*)d_in[13];
    const float* rope_c  = (const float*)d_in[14];
    const float* rope_s  = (const float*)d_in[15];
    float* out = (float*)d_out;

    float *qkv, *ctx, *y1, *x1, *hb;
    cudaGetSymbolAddress((void**)&qkv, g_qkv);
    cudaGetSymbolAddress((void**)&ctx, g_ctx);
    cudaGetSymbolAddress((void**)&y1,  g_y1);
    cudaGetSymbolAddress((void**)&x1,  g_x1);
    cudaGetSymbolAddress((void**)&hb,  g_h);

    static bool attr_set = false;
    if (!attr_set) {
        cudaFuncSetAttribute(attn_kernel,
                             cudaFuncAttributeMaxDynamicSharedMemorySize, ATT_SMEM);
        attr_set = true;
    }

    // 1. QKV projection + bias
    gemm_tf32<0><<<dim3(QKVC/128, NTOK/128), 256>>>(x, qkv_w, qkv_b, nullptr,
                                                    qkv, NTOK, Eq, QKVC);
    // 2. RoPE on q,k
    {
        int n = NTOK * Hq * (Dq/2);
        rope_kernel<<<(n + 255)/256, 256>>>(qkv, rope_c, rope_s);
    }
    // 3. attention
    attn_kernel<<<dim3(Sq/64, Hq, Bq), 256, ATT_SMEM>>>(qkv, mask, ctx);
    // 4. out-proj + bias + residual(x)
    gemm_tf32<2><<<dim3(Eq/128, NTOK/128), 256>>>(ctx, proj_w, proj_b, x,
                                                  y1, NTOK, Eq, Eq);
    // 5. LN1
    ln_kernel<<<NTOK, 256>>>(y1, ln1_g, ln1_b, x1);
    // 6. FC1 + bias + gelu
    gemm_tf32<1><<<dim3(Mq/128, NTOK/128), 256>>>(x1, w1, b1, nullptr,
                                                  hb, NTOK, Eq, Mq);
    // 7. FC2 + bias + residual(x1)
    gemm_tf32<2><<<dim3(Eq/128, NTOK/128), 256>>>(hb, w2, b2, x1,
                                                  out, NTOK, Mq, Eq);
    // 8. LN2 in-place
    ln_kernel<<<NTOK, 256>>>(out, ln2_g, ln2_b, out);
}

// round 4
// speedup vs baseline: 3.5627x; 1.2328x over previous
#include <cuda_runtime.h>
#include <cuda_bf16.h>
#include <cstdint>
#include <math.h>

#define Bq 8
#define Sq 1024
#define Eq 768
#define Hq 12
#define Dq 64
#define Mq 3072
#define NTOK (Bq*Sq)          // 8192
#define QKVC (3*Eq)           // 2304

// ---------------- scratch ----------------
__device__ float g_qkv[NTOK*QKVC];
__device__ float g_ctx[NTOK*Eq];
__device__ float g_y1 [NTOK*Eq];
__device__ float g_x1 [NTOK*Eq];
__device__ float g_h  [NTOK*Mq];

// ---------------- tf32 helpers ----------------
__device__ __forceinline__ unsigned f2tf32(float x) {
    unsigned u;
    asm("cvt.rna.tf32.f32 %0, %1;" : "=r"(u) : "f"(x));
    return u;
}
__device__ __forceinline__ float tf32f(float x) { return __uint_as_float(f2tf32(x)); }

__device__ __forceinline__ void mma_tf32(float* d, const unsigned* a, const unsigned* b) {
    asm volatile(
        "mma.sync.aligned.m16n8k8.row.col.f32.tf32.tf32.f32 "
        "{%0,%1,%2,%3}, {%4,%5,%6,%7}, {%8,%9}, {%0,%1,%2,%3};"
        : "+f"(d[0]), "+f"(d[1]), "+f"(d[2]), "+f"(d[3])
        : "r"(a[0]), "r"(a[1]), "r"(a[2]), "r"(a[3]),
          "r"(b[0]), "r"(b[1]));
}

__device__ __forceinline__ float ex2(float x) {
    float y;
    asm("ex2.approx.ftz.f32 %0, %1;" : "=f"(y) : "f"(x));
    return y;
}

// ---------------- tf32 tensor-core GEMM: C[N,Mo] = A[N,K] @ W[Mo,K]^T -------
// Block 128x128, BK=32, 256 threads (8 warps, 4x2 of 32x64 warp tiles).
// EPI: 0=+bias ; 1=+bias,gelu ; 2=+bias,+res ; 3=+bias,rope(q,k cols)
template<int EPI>
__global__ __launch_bounds__(256, 1)
void gemm_tf32(const float* __restrict__ A,
               const float* __restrict__ W,
               const float* __restrict__ bias,
               const float* __restrict__ res,
               const float* __restrict__ cosT,
               const float* __restrict__ sinT,
               float* __restrict__ C,
               int N, int K, int Mo)
{
    constexpr int KS = 36;
    __shared__ float As[128 * KS];
    __shared__ float Bs[128 * KS];

    const int tid  = threadIdx.x;
    const int warp = tid >> 5, lane = tid & 31;
    const int g    = lane >> 2, t4 = lane & 3;
    const int wm   = warp >> 1, wn = warp & 1;
    const int m0w  = wm * 32,  n0w = wn * 64;
    const int bm0  = blockIdx.y * 128;
    const int bn0  = blockIdx.x * 128;

    const int arow = tid >> 1;
    const int acol = (tid & 1) * 16;

    const float* Ap = A + (size_t)(bm0 + arow) * K + acol;
    const float* Wp = W + (size_t)(bn0 + arow) * K + acol;

    float acc[2][8][4];
    #pragma unroll
    for (int mi = 0; mi < 2; mi++)
        #pragma unroll
        for (int ni = 0; ni < 8; ni++)
            #pragma unroll
            for (int r = 0; r < 4; r++) acc[mi][ni][r] = 0.f;

    float4 pa[4], pb[4];
    #pragma unroll
    for (int u = 0; u < 4; u++) {
        pa[u] = *(const float4*)(Ap + u * 4);
        pb[u] = *(const float4*)(Wp + u * 4);
    }

    const int T = K / 32;
    for (int t = 0; t < T; t++) {
        #pragma unroll
        for (int u = 0; u < 4; u++) {
            float4 ca, cb;
            ca.x = tf32f(pa[u].x); ca.y = tf32f(pa[u].y);
            ca.z = tf32f(pa[u].z); ca.w = tf32f(pa[u].w);
            cb.x = tf32f(pb[u].x); cb.y = tf32f(pb[u].y);
            cb.z = tf32f(pb[u].z); cb.w = tf32f(pb[u].w);
            *(float4*)&As[arow * KS + acol + u * 4] = ca;
            *(float4*)&Bs[arow * KS + acol + u * 4] = cb;
        }
        __syncthreads();

        if (t + 1 < T) {
            const float* Ap2 = Ap + (t + 1) * 32;
            const float* Wp2 = Wp + (t + 1) * 32;
            #pragma unroll
            for (int u = 0; u < 4; u++) {
                pa[u] = *(const float4*)(Ap2 + u * 4);
                pb[u] = *(const float4*)(Wp2 + u * 4);
            }
        }

        #pragma unroll
        for (int kk = 0; kk < 32; kk += 8) {
            unsigned af[2][4], bf[8][2];
            #pragma unroll
            for (int mi = 0; mi < 2; mi++) {
                const int mr = m0w + mi * 16;
                af[mi][0] = __float_as_uint(As[(mr + g)     * KS + kk + t4]);
                af[mi][1] = __float_as_uint(As[(mr + g + 8) * KS + kk + t4]);
                af[mi][2] = __float_as_uint(As[(mr + g)     * KS + kk + t4 + 4]);
                af[mi][3] = __float_as_uint(As[(mr + g + 8) * KS + kk + t4 + 4]);
            }
            #pragma unroll
            for (int ni = 0; ni < 8; ni++) {
                const int nr = n0w + ni * 8 + g;
                bf[ni][0] = __float_as_uint(Bs[nr * KS + kk + t4]);
                bf[ni][1] = __float_as_uint(Bs[nr * KS + kk + t4 + 4]);
            }
            #pragma unroll
            for (int mi = 0; mi < 2; mi++)
                #pragma unroll
                for (int ni = 0; ni < 8; ni++)
                    mma_tf32(acc[mi][ni], af[mi], bf[ni]);
        }
        __syncthreads();
    }

    #pragma unroll
    for (int mi = 0; mi < 2; mi++) {
        #pragma unroll
        for (int half = 0; half < 2; half++) {
            const int m = bm0 + m0w + mi * 16 + g + half * 8;
            #pragma unroll
            for (int ni = 0; ni < 8; ni++) {
                const int n = bn0 + n0w + ni * 8 + 2 * t4;
                float v0 = acc[mi][ni][half * 2 + 0] + bias[n];
                float v1 = acc[mi][ni][half * 2 + 1] + bias[n + 1];
                if (EPI == 1) {
                    v0 = 0.5f * v0 * (1.0f + erff(v0 * 0.70710678118654752f));
                    v1 = 0.5f * v1 * (1.0f + erff(v1 * 0.70710678118654752f));
                }
                if (EPI == 2) {
                    float2 rv = *(const float2*)(res + (size_t)m * Mo + n);
                    v0 += rv.x; v1 += rv.y;
                }
                if (EPI == 3) {
                    if (n < 2 * Eq) {          // rotary on q and k columns
                        const int srow = m & (Sq - 1);
                        const int c    = n & (Dq - 1);   // even
                        float2 cc = *(const float2*)(cosT + srow * Dq + c);
                        float2 ss = *(const float2*)(sinT + srow * Dq + c);
                        float r0 = v0 * cc.x - v1 * ss.x;
                        float r1 = v1 * cc.y + v0 * ss.y;
                        v0 = r0; v1 = r1;
                    }
                }
                float2 ov; ov.x = v0; ov.y = v1;
                *(float2*)(C + (size_t)m * Mo + n) = ov;
            }
        }
    }
}

// ---------------- tensor-core flash attention -------------------------------
// block = (64 q rows, head, batch); 128 threads = 4 warps, warp w owns
// q-rows [w*16, w*16+16). tf32 mma for QK^T and P@V, fp32 online softmax.
#define KT_STR 72     // KsT[d][key] & Vs[key][d] stride: conflict-free B-frag reads
#define PS_STR 68     // per-warp P tile stride: conflict-free A-frag reads
#define ATTN_SMEM ((2*64*KT_STR + 4*16*PS_STR) * 4)

__global__ __launch_bounds__(128, 3)
void attn_mma(const float* __restrict__ qkv,
              const unsigned char* __restrict__ mask,
              float* __restrict__ ctx)
{
    extern __shared__ float sm[];
    float* KsT = sm;                    // [64 d][64 key]
    float* Vs  = sm + 64 * KT_STR;      // [64 key][64 d]
    float* Ps  = sm + 2 * 64 * KT_STR;  // per-warp [16][PS_STR]

    const int tid  = threadIdx.x;
    const int warp = tid >> 5, lane = tid & 31;
    const int g    = lane >> 2, t4 = lane & 3;
    const int b = blockIdx.z, h = blockIdx.y;
    const int q0 = blockIdx.x * 64;
    float* Pw = Ps + warp * 16 * PS_STR;

    // Q fragments (persistent in registers), tf32-rounded
    unsigned aQ[8][4];
    {
        const float* qp = qkv + (size_t)(b * Sq + q0 + warp * 16) * QKVC + h * Dq;
        #pragma unroll
        for (int s = 0; s < 8; s++) {
            aQ[s][0] = f2tf32(qp[(size_t)g       * QKVC + 8*s + t4]);
            aQ[s][1] = f2tf32(qp[(size_t)(g + 8) * QKVC + 8*s + t4]);
            aQ[s][2] = f2tf32(qp[(size_t)g       * QKVC + 8*s + t4 + 4]);
            aQ[s][3] = f2tf32(qp[(size_t)(g + 8) * QKVC + 8*s + t4 + 4]);
        }
    }

    float m0 = -1e30f, m1 = -1e30f, l0 = 0.f, l1 = 0.f;
    float O[8][4];
    #pragma unroll
    for (int ni = 0; ni < 8; ni++)
        #pragma unroll
        for (int r = 0; r < 4; r++) O[ni][r] = 0.f;

    const float SC = 0.125f * 1.4426950408889634f;  // head-scale * log2(e)

    for (int k0 = 0; k0 < Sq; k0 += 64) {
        __syncthreads();
        // load K (transposed, tf32) and V (row-major, tf32)
        {
            const int key = tid >> 1;
            const int dh  = (tid & 1) * 32;
            const float* kp = qkv + (size_t)(b * Sq + k0 + key) * QKVC + Eq + h * Dq + dh;
            #pragma unroll
            for (int u = 0; u < 8; u++) {
                float4 kv = *(const float4*)(kp + u * 4);
                float4 vv = *(const float4*)(kp + Eq + u * 4);
                const int d = dh + u * 4;
                KsT[(d + 0) * KT_STR + key] = tf32f(kv.x);
                KsT[(d + 1) * KT_STR + key] = tf32f(kv.y);
                KsT[(d + 2) * KT_STR + key] = tf32f(kv.z);
                KsT[(d + 3) * KT_STR + key] = tf32f(kv.w);
                float4 cv;
                cv.x = tf32f(vv.x); cv.y = tf32f(vv.y);
                cv.z = tf32f(vv.z); cv.w = tf32f(vv.w);
                *(float4*)&Vs[key * KT_STR + d] = cv;
            }
        }
        __syncthreads();

        // S = Q @ K^T  (per warp: 16 x 64)
        float sacc[8][4];
        #pragma unroll
        for (int ni = 0; ni < 8; ni++)
            #pragma unroll
            for (int r = 0; r < 4; r++) sacc[ni][r] = 0.f;

        #pragma unroll
        for (int ni = 0; ni < 8; ni++) {
            const int keyc = ni * 8 + g;
            #pragma unroll
            for (int s = 0; s < 8; s++) {
                unsigned bk[2];
                bk[0] = __float_as_uint(KsT[(8*s + t4)     * KT_STR + keyc]);
                bk[1] = __float_as_uint(KsT[(8*s + t4 + 4) * KT_STR + keyc]);
                mma_tf32(sacc[ni], aQ[s], bk);
            }
        }

        // scale + mask + row max
        const unsigned char* mp = mask + b * Sq + k0;
        float mx0 = -1e30f, mx1 = -1e30f;
        #pragma unroll
        for (int ni = 0; ni < 8; ni++) {
            const bool k0m = mp[ni * 8 + 2 * t4];
            const bool k1m = mp[ni * 8 + 2 * t4 + 1];
            float v0 = k0m ? -1e30f : sacc[ni][0] * SC;
            float v1 = k1m ? -1e30f : sacc[ni][1] * SC;
            float v2 = k0m ? -1e30f : sacc[ni][2] * SC;
            float v3 = k1m ? -1e30f : sacc[ni][3] * SC;
            sacc[ni][0] = v0; sacc[ni][1] = v1;
            sacc[ni][2] = v2; sacc[ni][3] = v3;
            mx0 = fmaxf(mx0, fmaxf(v0, v1));
            mx1 = fmaxf(mx1, fmaxf(v2, v3));
        }
        mx0 = fmaxf(mx0, __shfl_xor_sync(0xffffffffu, mx0, 1));
        mx0 = fmaxf(mx0, __shfl_xor_sync(0xffffffffu, mx0, 2));
        mx1 = fmaxf(mx1, __shfl_xor_sync(0xffffffffu, mx1, 1));
        mx1 = fmaxf(mx1, __shfl_xor_sync(0xffffffffu, mx1, 2));

        const float mn0 = fmaxf(m0, mx0), mn1 = fmaxf(m1, mx1);
        float ps0 = 0.f, ps1 = 0.f;
        #pragma unroll
        for (int ni = 0; ni < 8; ni++) {
            float p0 = ex2(sacc[ni][0] - mn0);
            float p1 = ex2(sacc[ni][1] - mn0);
            float p2 = ex2(sacc[ni][2] - mn1);
            float p3 = ex2(sacc[ni][3] - mn1);
            ps0 += p0 + p1; ps1 += p2 + p3;
            float2 w0; w0.x = tf32f(p0); w0.y = tf32f(p1);
            float2 w1; w1.x = tf32f(p2); w1.y = tf32f(p3);
            *(float2*)&Pw[g       * PS_STR + ni * 8 + 2 * t4] = w0;
            *(float2*)&Pw[(g + 8) * PS_STR + ni * 8 + 2 * t4] = w1;
        }
        ps0 += __shfl_xor_sync(0xffffffffu, ps0, 1);
        ps0 += __shfl_xor_sync(0xffffffffu, ps0, 2);
        ps1 += __shfl_xor_sync(0xffffffffu, ps1, 1);
        ps1 += __shfl_xor_sync(0xffffffffu, ps1, 2);

        const float c0 = ex2(m0 - mn0), c1 = ex2(m1 - mn1);
        l0 = l0 * c0 + ps0; l1 = l1 * c1 + ps1;
        m0 = mn0; m1 = mn1;
        #pragma unroll
        for (int ni = 0; ni < 8; ni++) {
            O[ni][0] *= c0; O[ni][1] *= c0;
            O[ni][2] *= c1; O[ni][3] *= c1;
        }
        __syncwarp();

        // O += P @ V
        #pragma unroll
        for (int s = 0; s < 8; s++) {
            unsigned aP[4];
            aP[0] = __float_as_uint(Pw[g       * PS_STR + 8*s + t4]);
            aP[1] = __float_as_uint(Pw[(g + 8) * PS_STR + 8*s + t4]);
            aP[2] = __float_as_uint(Pw[g       * PS_STR + 8*s + t4 + 4]);
            aP[3] = __float_as_uint(Pw[(g + 8) * PS_STR + 8*s + t4 + 4]);
            #pragma unroll
            for (int ni = 0; ni < 8; ni++) {
                unsigned bv[2];
                bv[0] = __float_as_uint(Vs[(8*s + t4)     * KT_STR + ni * 8 + g]);
                bv[1] = __float_as_uint(Vs[(8*s + t4 + 4) * KT_STR + ni * 8 + g]);
                mma_tf32(O[ni], aP, bv);
            }
        }
    }

    // write out: ctx[token][h*64 + d]
    const float inv0 = 1.f / l0, inv1 = 1.f / l1;
    float* op0 = ctx + ((size_t)(b * Sq + q0 + warp * 16 + g)     * Hq + h) * Dq;
    float* op1 = ctx + ((size_t)(b * Sq + q0 + warp * 16 + g + 8) * Hq + h) * Dq;
    #pragma unroll
    for (int ni = 0; ni < 8; ni++) {
        float2 o0; o0.x = O[ni][0] * inv0; o0.y = O[ni][1] * inv0;
        float2 o1; o1.x = O[ni][2] * inv1; o1.y = O[ni][3] * inv1;
        *(float2*)(op0 + ni * 8 + 2 * t4) = o0;
        *(float2*)(op1 + ni * 8 + 2 * t4) = o1;
    }
}

// ---------------- LayerNorm (768) ----------------
__global__ void ln_kernel(const float* __restrict__ in,
                          const float* __restrict__ g,
                          const float* __restrict__ b,
                          float* __restrict__ out)
{
    const int row = blockIdx.x;
    const int t   = threadIdx.x;
    const float* p = in + (size_t)row * Eq;

    float v0 = p[t], v1 = p[t + 256], v2 = p[t + 512];
    float s  = v0 + v1 + v2;
    float s2 = v0*v0 + v1*v1 + v2*v2;
    #pragma unroll
    for (int o = 16; o; o >>= 1) {
        s  += __shfl_xor_sync(0xffffffffu, s,  o);
        s2 += __shfl_xor_sync(0xffffffffu, s2, o);
    }
    __shared__ float sh[2][8];
    if ((t & 31) == 0) { sh[0][t >> 5] = s; sh[1][t >> 5] = s2; }
    __syncthreads();
    float ts = 0.f, ts2 = 0.f;
    #pragma unroll
    for (int i = 0; i < 8; i++) { ts += sh[0][i]; ts2 += sh[1][i]; }

    const float mean = ts * (1.f / Eq);
    const float var  = ts2 * (1.f / Eq) - mean * mean;
    const float r    = rsqrtf(var + 1e-5f);

    float* o = out + (size_t)row * Eq;
    o[t]       = (v0 - mean) * r * g[t]       + b[t];
    o[t + 256] = (v1 - mean) * r * g[t + 256] + b[t + 256];
    o[t + 512] = (v2 - mean) * r * g[t + 512] + b[t + 512];
}

// ------------------------------- launch ---------------------------------------
extern "C" void kernel_launch(void* const* d_in, const int* in_sizes, int n_in,
                              void* d_out, int out_size)
{
    const float* x       = (const float*)d_in[0];
    const unsigned char* mask = (const unsigned char*)d_in[1];
    const float* qkv_w   = (const float*)d_in[2];
    const float* qkv_b   = (const float*)d_in[3];
    const float* proj_w  = (const float*)d_in[4];
    const float* proj_b  = (const float*)d_in[5];
    const float* ln1_g   = (const float*)d_in[6];
    const float* ln1_b   = (const float*)d_in[7];
    const float* w1      = (const float*)d_in[8];
    const float* b1      = (const float*)d_in[9];
    const float* w2      = (const float*)d_in[10];
    const float* b2      = (const float*)d_in[11];
    const float* ln2_g   = (const float*)d_in[12];
    const float* ln2_b   = (const float*)d_in[13];
    const float* rope_c  = (const float*)d_in[14];
    const float* rope_s  = (const float*)d_in[15];
    float* out = (float*)d_out;

    float *qkv, *ctx, *y1, *x1, *hb;
    cudaGetSymbolAddress((void**)&qkv, g_qkv);
    cudaGetSymbolAddress((void**)&ctx, g_ctx);
    cudaGetSymbolAddress((void**)&y1,  g_y1);
    cudaGetSymbolAddress((void**)&x1,  g_x1);
    cudaGetSymbolAddress((void**)&hb,  g_h);

    static bool attr_set = false;
    if (!attr_set) {
        cudaFuncSetAttribute(attn_mma,
                             cudaFuncAttributeMaxDynamicSharedMemorySize, ATTN_SMEM);
        attr_set = true;
    }

    // 1. QKV projection + bias + fused 2D RoPE
    gemm_tf32<3><<<dim3(QKVC/128, NTOK/128), 256>>>(x, qkv_w, qkv_b, nullptr,
                                                    rope_c, rope_s,
                                                    qkv, NTOK, Eq, QKVC);
    // 2. tensor-core flash attention
    attn_mma<<<dim3(Sq/64, Hq, Bq), 128, ATTN_SMEM>>>(qkv, mask, ctx);
    // 3. out-proj + bias + residual(x)
    gemm_tf32<2><<<dim3(Eq/128, NTOK/128), 256>>>(ctx, proj_w, proj_b, x,
                                                  nullptr, nullptr,
                                                  y1, NTOK, Eq, Eq);
    // 4. LN1
    ln_kernel<<<NTOK, 256>>>(y1, ln1_g, ln1_b, x1);
    // 5. FC1 + bias + gelu
    gemm_tf32<1><<<dim3(Mq/128, NTOK/128), 256>>>(x1, w1, b1, nullptr,
                                                  nullptr, nullptr,
                                                  hb, NTOK, Eq, Mq);
    // 6. FC2 + bias + residual(x1)
    gemm_tf32<2><<<dim3(Eq/128, NTOK/128), 256>>>(hb, w2, b2, x1,
                                                  nullptr, nullptr,
                                                  out, NTOK, Mq, Eq);
    // 7. LN2 in-place
    ln_kernel<<<NTOK, 256>>>(out, ln2_g, ln2_b, out);
}